// round 7
// baseline (speedup 1.0000x reference)
#include <cuda_runtime.h>
#include <math.h>

#define NQ 10
#define NP 100
#define FD 256
#define NOUT 30
#define TWO_PI_F 6.2831853071795864769f

typedef unsigned long long u64;

// Cross-CTA scratch + per-pair arrival counters (zero-init; the combining CTA
// resets its counter each launch so graph replays see clean state).
__device__ float g_mres[3][256][32];
__device__ int   g_cnt[128];

// ---- f32x2 packed helpers (lane = (sample0, sample1)) ----
__device__ __forceinline__ u64 pack2(float a, float b) {
    u64 r; asm("mov.b64 %0, {%1,%2};" : "=l"(r) : "f"(a), "f"(b)); return r;
}
__device__ __forceinline__ void unpack2(u64 v, float& a, float& b) {
    asm("mov.b64 {%0,%1}, %2;" : "=f"(a), "=f"(b) : "l"(v));
}
__device__ __forceinline__ u64 fma2(u64 a, u64 b, u64 c) {
    u64 d; asm("fma.rn.f32x2 %0, %1, %2, %3;" : "=l"(d) : "l"(a), "l"(b), "l"(c));
    return d;
}
__device__ __forceinline__ u64 mul2(u64 a, u64 b) {
    u64 d; asm("mul.rn.f32x2 %0, %1, %2;" : "=l"(d) : "l"(a), "l"(b)); return d;
}
__device__ __forceinline__ u64 add2(u64 a, u64 b) {
    u64 d; asm("add.rn.f32x2 %0, %1, %2;" : "=l"(d) : "l"(a), "l"(b)); return d;
}
__device__ __forceinline__ u64 neg2(u64 a) { return a ^ 0x8000000080000000ull; }
__device__ __forceinline__ u64 shfl2(u64 v, int m) {
    return __shfl_xor_sync(0xffffffffu, v, m);
}
__device__ __forceinline__ u64 bfly2(u64 v) {
#pragma unroll
    for (int o = 16; o; o >>= 1) v = add2(v, shfl2(v, o));
    return v;
}

// ---------------------------------------------------------------------------
// One CTA = one (sample-pair, branch). 256 threads, 4 amp-pairs/thread.
// amp = (tid << 2) | j : j bits 0-1 local, tid bits 0-4 lane (amp bits 2-6),
// tid bits 5-7 cross-warp (amp bits 7-9, via smem).
// ---------------------------------------------------------------------------

// Fused SU(2) gate on amp-bit b. U = [[u00,u01],[-conj(u01),conj(u00)]]
__device__ __forceinline__ void apply_u2(int b, u64 u00r, u64 u00i,
                                         u64 u01r, u64 u01i,
                                         u64 ar[4], u64 ai[4],
                                         int tid, u64* BA, u64* BI) {
    if (b < 2) {                                  // local register pairs
        const u64 nu00i = neg2(u00i), nu01r = neg2(u01r), nu01i = neg2(u01i);
#pragma unroll
        for (int t = 0; t < 2; t++) {
            int j0 = (b == 0) ? t * 2 : t;
            int j1 = j0 | (1 << b);
            u64 r0 = ar[j0], i0 = ai[j0], r1 = ar[j1], i1 = ai[j1];
            ar[j0] = fma2(u00r, r0, fma2(nu00i, i0, fma2(u01r, r1, mul2(nu01i, i1))));
            ai[j0] = fma2(u00r, i0, fma2(u00i,  r0, fma2(u01r, i1, mul2(u01i,  r1))));
            ar[j1] = fma2(nu01r, r0, fma2(nu01i, i0, fma2(u00r, r1, mul2(u00i, i1))));
            ai[j1] = fma2(nu01r, i0, fma2(u01i,  r0, fma2(u00r, i1, mul2(nu00i, r1))));
        }
    } else if (b < 7) {                           // lane bits: warp shuffle
        const int m = 1 << (b - 2);
        const int s = (tid >> (b - 2)) & 1;
        const u64 cwr = u00r;
        const u64 cwi = s ? neg2(u00i) : u00i;
        const u64 cpr = s ? neg2(u01r) : u01r;
        const u64 cpi = u01i;
        const u64 ncwi = neg2(cwi), ncpi = neg2(cpi);
#pragma unroll
        for (int j = 0; j < 4; j++) {
            u64 pr = shfl2(ar[j], m);
            u64 pi = shfl2(ai[j], m);
            u64 orr = ar[j], oii = ai[j];
            ar[j] = fma2(cwr, orr, fma2(ncwi, oii, fma2(cpr, pr, mul2(ncpi, pi))));
            ai[j] = fma2(cwr, oii, fma2(cwi,  orr, fma2(cpr, pi, mul2(cpi,  pr))));
        }
    } else {                                      // cross-warp bits: smem
        const int m = 1 << (b - 2);
        const int s = (tid >> (b - 2)) & 1;
#pragma unroll
        for (int j = 0; j < 4; j++) {
            BA[(tid << 2) | j] = ar[j];
            BI[(tid << 2) | j] = ai[j];
        }
        __syncthreads();
        const int pt = tid ^ m;
        const u64 cwr = u00r;
        const u64 cwi = s ? neg2(u00i) : u00i;
        const u64 cpr = s ? neg2(u01r) : u01r;
        const u64 cpi = u01i;
        const u64 ncwi = neg2(cwi), ncpi = neg2(cpi);
#pragma unroll
        for (int j = 0; j < 4; j++) {
            u64 pr = BA[(pt << 2) | j];
            u64 pi = BI[(pt << 2) | j];
            u64 orr = ar[j], oii = ai[j];
            ar[j] = fma2(cwr, orr, fma2(ncwi, oii, fma2(cpr, pr, mul2(ncpi, pi))));
            ai[j] = fma2(cwr, oii, fma2(cwi,  orr, fma2(cpr, pi, mul2(cpi,  pr))));
        }
        __syncthreads();
    }
}

// Controlled-RX: control bit pc, target bit pt. c2/s2 packed (cos,sin)(th/2).
__device__ __forceinline__ void apply_crx2(int pc, int pt, u64 c2, u64 s2,
                                           u64 ar[4], u64 ai[4],
                                           int tid, u64* BA, u64* BI) {
    const u64 ns2 = neg2(s2);
    const bool tc = (pc >= 2) ? (((tid >> (pc - 2)) & 1) != 0) : true;
    if (pt < 2) {                                 // local target
#pragma unroll
        for (int t = 0; t < 2; t++) {
            int j0 = (pt == 0) ? t * 2 : t;
            int j1 = j0 | (1 << pt);
            bool upd = tc && (pc < 2 ? (((j0 >> pc) & 1) != 0) : true);
            if (upd) {
                u64 r0 = ar[j0], i0 = ai[j0], r1 = ar[j1], i1 = ai[j1];
                ar[j0] = fma2(c2, r0, mul2(s2,  i1));
                ai[j0] = fma2(c2, i0, mul2(ns2, r1));
                ar[j1] = fma2(c2, r1, mul2(s2,  i0));
                ai[j1] = fma2(c2, i1, mul2(ns2, r0));
            }
        }
    } else if (pt < 7) {                          // lane target: shuffle
        const int m = 1 << (pt - 2);
#pragma unroll
        for (int j = 0; j < 4; j++) {
            u64 pr = shfl2(ar[j], m);
            u64 pi = shfl2(ai[j], m);
            bool upd = tc && (pc < 2 ? (((j >> pc) & 1) != 0) : true);
            if (upd) {
                u64 orr = ar[j], oii = ai[j];
                ar[j] = fma2(c2, orr, mul2(s2,  pi));
                ai[j] = fma2(c2, oii, mul2(ns2, pr));
            }
        }
    } else {                                      // cross-warp target: smem
        const int m = 1 << (pt - 2);
#pragma unroll
        for (int j = 0; j < 4; j++) {
            BA[(tid << 2) | j] = ar[j];
            BI[(tid << 2) | j] = ai[j];
        }
        __syncthreads();
        const int ptn = tid ^ m;
#pragma unroll
        for (int j = 0; j < 4; j++) {
            u64 pr = BA[(ptn << 2) | j];
            u64 pi = BI[(ptn << 2) | j];
            bool upd = tc && (pc < 2 ? (((j >> pc) & 1) != 0) : true);
            if (upd) {
                u64 orr = ar[j], oii = ai[j];
                ar[j] = fma2(c2, orr, mul2(s2,  pi));
                ai[j] = fma2(c2, oii, mul2(ns2, pr));
            }
        }
        __syncthreads();
    }
}

__global__ __launch_bounds__(256, 3)
void qsb_pair_kernel(const float* __restrict__ x,
                     const float* __restrict__ W1, const float* __restrict__ b1,
                     const float* __restrict__ W2, const float* __restrict__ b2,
                     const float* __restrict__ W3, const float* __restrict__ b3,
                     const float* __restrict__ base1, const float* __restrict__ base2,
                     const float* __restrict__ base3,
                     const float* __restrict__ alpha_r, const float* __restrict__ alpha_i,
                     const float* __restrict__ beta_r,  const float* __restrict__ beta_i,
                     const float* __restrict__ gamma_r, const float* __restrict__ gamma_i,
                     float* __restrict__ out) {
    __shared__ float sxA[FD], sxB[FD];
    __shared__ u64 rawu[NP];                      // packed GEMV pre-activation
    __shared__ float gcp[NP][2], gsp[NP][2];      // per-sample cos/sin(theta/2)
    __shared__ u64 BA[1024], BI[1024];            // exchange / dump buffers
    __shared__ u64 wred2[8][NOUT];
    __shared__ int flag;

    const int tid   = threadIdx.x;
    const int lane  = tid & 31;
    const int warp  = tid >> 5;
    const int pairI = blockIdx.x;                 // 0..127
    const int g     = blockIdx.y;                 // branch 0..2
    const int b0    = pairI << 1;                 // samples b0, b0+1

    sxA[tid] = x[b0 * FD + tid];
    sxB[tid] = x[(b0 + 1) * FD + tid];

    const float* W  = (g == 0) ? W1 : ((g == 1) ? W2 : W3);
    const float* bb = (g == 0) ? b1 : ((g == 1) ? b2 : b3);
    const float* ba = (g == 0) ? base1 : ((g == 1) ? base2 : base3);
    __syncthreads();

    // ---- GEMV: warp-per-row, both samples per pass ----
    {
        const float4* xav = (const float4*)sxA;
        const float4* xbv = (const float4*)sxB;
        const float4 xa0 = xav[lane * 2], xa1 = xav[lane * 2 + 1];
        const float4 xb0 = xbv[lane * 2], xb1 = xbv[lane * 2 + 1];
        const float4* Wv = (const float4*)W;
        for (int p = warp; p < NP; p += 8) {
            float4 w0 = Wv[p * 64 + lane * 2];
            float4 w1 = Wv[p * 64 + lane * 2 + 1];
            float a0 = w0.x * xa0.x + w0.y * xa0.y + w0.z * xa0.z + w0.w * xa0.w
                     + w1.x * xa1.x + w1.y * xa1.y + w1.z * xa1.z + w1.w * xa1.w;
            float a1 = w0.x * xb0.x + w0.y * xb0.y + w0.z * xb0.z + w0.w * xb0.w
                     + w1.x * xb1.x + w1.y * xb1.y + w1.z * xb1.z + w1.w * xb1.w;
            u64 acc = bfly2(pack2(a0, a1));
            if (lane == 0) rawu[p] = acc;
        }
    }
    __syncthreads();
    // ---- activations (200 work items: sample s, param p) ----
    if (tid < 200) {
        const int s = tid >= NP;
        const int p = tid - (s ? NP : 0);
        float vA, vB; unpack2(rawu[p], vA, vB);
        float t   = (s ? vB : vA) + bb[p] + ba[p];
        float sig = 1.f / (1.f + __expf(-t));
        float sv, cv;
        __sincosf(0.5f * sig * TWO_PI_F, &sv, &cv);
        gcp[p][s] = cv; gsp[p][s] = sv;
    }

    // ---- state: 4 packed amp-pairs per thread ----
    u64 ar[4], ai[4];
#pragma unroll
    for (int j = 0; j < 4; j++) { ar[j] = 0; ai[j] = 0; }
    if (tid == 0) ar[0] = pack2(1.f, 1.f);
    __syncthreads();

    int idx = 0;
#pragma unroll
    for (int layer = 0; layer < 2; layer++) {
#pragma unroll
        for (int w = 0; w < NQ; w++) {
            u64 c0 = pack2(gcp[idx][0],     gcp[idx][1]);
            u64 s0 = pack2(gsp[idx][0],     gsp[idx][1]);
            u64 c1 = pack2(gcp[idx + 1][0], gcp[idx + 1][1]);
            u64 s1 = pack2(gsp[idx + 1][0], gsp[idx + 1][1]);
            u64 cz = pack2(gcp[idx + 2][0], gcp[idx + 2][1]);
            u64 sz = pack2(gsp[idx + 2][0], gsp[idx + 2][1]);
            idx += 3;
            // Fused U = Rz*Ry*Rx
            u64 t1 = mul2(cz, c1);   // cz*c1
            u64 t2 = mul2(sz, s1);   // sz*s1
            u64 t3 = mul2(cz, s1);   // cz*s1
            u64 t4 = mul2(sz, c1);   // sz*c1
            u64 u00r = fma2(t1, c0, mul2(t2, s0));          //  cz c1 c0 + sz s1 s0
            u64 u00i = fma2(neg2(t4), c0, mul2(t3, s0));    //  cz s1 s0 - sz c1 c0
            u64 u01r = neg2(fma2(t3, c0, mul2(t4, s0)));    // -(cz s1 c0 + sz c1 s0)
            u64 u01i = fma2(neg2(t1), s0, mul2(t2, c0));    //  sz s1 c0 - cz c1 s0
            apply_u2(9 - w, u00r, u00i, u01r, u01i, ar, ai, tid, BA, BI);
        }
#pragma unroll
        for (int i = 0; i < NQ; i++) {
            u64 c2 = pack2(gcp[idx][0], gcp[idx][1]);
            u64 s2 = pack2(gsp[idx][0], gsp[idx][1]);
            apply_crx2(9 - i, 9 - ((i + 1) % NQ), c2, s2, ar, ai, tid, BA, BI);
            idx++;
        }
#pragma unroll
        for (int i = NQ - 1; i >= 0; i--) {
            u64 c2 = pack2(gcp[idx][0], gcp[idx][1]);
            u64 s2 = pack2(gsp[idx][0], gsp[idx][1]);
            apply_crx2(9 - i, 9 - ((i + 9) % NQ), c2, s2, ar, ai, tid, BA, BI);
            idx++;
        }
    }

    // ---- dump state, expectations (packed) ----
#pragma unroll
    for (int j = 0; j < 4; j++) {
        BA[(tid << 2) | j] = ar[j];
        BI[(tid << 2) | j] = ai[j];
    }
    __syncthreads();
#pragma unroll
    for (int w = 0; w < NQ; w++) {
        const int p = 9 - w;
        u64 zr = 0, zi = 0, pz = 0;
#pragma unroll
        for (int kk = 0; kk < 2; kk++) {
            int k  = tid + kk * 256;
            int i0 = ((k >> p) << (p + 1)) | (k & ((1 << p) - 1));
            int i1 = i0 | (1 << p);
            u64 r0 = BA[i0], m0 = BI[i0];
            u64 r1 = BA[i1], m1 = BI[i1];
            zr = fma2(r0, r1, fma2(m0, m1, zr));
            zi = fma2(r0, m1, fma2(neg2(m0), r1, zi));
            pz = fma2(r0, r0, fma2(m0, m0,
                 fma2(neg2(r1), r1, fma2(neg2(m1), m1, pz))));
        }
        zr = bfly2(zr); zi = bfly2(zi); pz = bfly2(pz);
        if (lane == 0) {
            wred2[warp][w]          = zr;
            wred2[warp][NQ + w]     = zi;
            wred2[warp][2 * NQ + w] = pz;
        }
    }
    __syncthreads();
    if (tid < NOUT) {
        u64 a = wred2[0][tid];
#pragma unroll
        for (int q = 1; q < 8; q++) a = add2(a, wred2[q][tid]);
        float vA, vB; unpack2(a, vA, vB);
        float sc = (tid < 2 * NQ) ? 2.f : 1.f;
        g_mres[g][b0][tid]     = sc * vA;
        g_mres[g][b0 + 1][tid] = sc * vB;
    }

    // ---- last-arriving branch combines ----
    __threadfence();
    __syncthreads();
    if (tid == 0) {
        int old = atomicAdd(&g_cnt[pairI], 1);
        flag = (old == 2);
        if (old == 2) g_cnt[pairI] = 0;           // restore for next replay
    }
    __syncthreads();
    if (flag) {
        __threadfence();
        if (tid < 2 * NOUT) {
            const int s   = tid >= NOUT;
            const int o   = tid - (s ? NOUT : 0);
            const int bat = b0 + s;
            float arv = alpha_r[0], aiv = alpha_i[0];
            float brv = beta_r[0],  biv = beta_i[0];
            float grv = gamma_r[0], giv = gamma_i[0];
            float nrm = sqrtf(arv * arv + aiv * aiv + brv * brv + biv * biv +
                              grv * grv + giv * giv + 1e-9f);
            float inv = 1.f / nrm;
            float m0 = g_mres[0][bat][o];
            float m1 = g_mres[1][bat][o];
            float m2 = g_mres[2][bat][o];
            float re = (arv * m0 + brv * m1 + grv * m2) * inv;
            float im = (aiv * m0 + biv * m1 + giv * m2) * inv;
            out[bat * NOUT + o] = sqrtf(re * re + im * im);
        }
    }
}

extern "C" void kernel_launch(void* const* d_in, const int* in_sizes, int n_in,
                              void* d_out, int out_size) {
    const float* x      = (const float*)d_in[0];
    const float* W1     = (const float*)d_in[1];
    const float* b1     = (const float*)d_in[2];
    const float* W2     = (const float*)d_in[3];
    const float* b2     = (const float*)d_in[4];
    const float* W3     = (const float*)d_in[5];
    const float* b3     = (const float*)d_in[6];
    const float* base1  = (const float*)d_in[7];
    const float* base2  = (const float*)d_in[8];
    const float* base3  = (const float*)d_in[9];
    const float* ar     = (const float*)d_in[10];
    const float* ai     = (const float*)d_in[11];
    const float* br     = (const float*)d_in[12];
    const float* bi     = (const float*)d_in[13];
    const float* gr     = (const float*)d_in[14];
    const float* gi     = (const float*)d_in[15];
    float* out = (float*)d_out;

    dim3 grid(128, 3);                            // 128 sample-pairs x 3 branches
    qsb_pair_kernel<<<grid, 256>>>(x, W1, b1, W2, b2, W3, b3,
                                   base1, base2, base3,
                                   ar, ai, br, bi, gr, gi, out);
}